// round 8
// baseline (speedup 1.0000x reference)
#include <cuda_runtime.h>
#include <math.h>

#define IN_DIM 8
#define HID 50
#define KTOT 58            // 50 h-rows + 8 x-rows unified
#define BATCH 4096
#define TLEN 512
#define ROWS 150
#define RPAD 164
#define NBG 16             // batches per group
#define NT 256
#define GRIDN (BATCH / 32)
#define HXS (KTOT * NBG)   // one hx buffer (per group)
#define WPT 12             // Wp floats per tile (48B stride: conflict-free for 8-tile warps)

typedef unsigned long long ull;

__device__ __forceinline__ ull pk2(float a) {
    ull r; asm("mov.b64 %0, {%1, %1};" : "=l"(r) : "f"(a)); return r;
}
__device__ __forceinline__ ull ff2(ull a, ull b, ull c) {
    ull d; asm("fma.rn.f32x2 %0, %1, %2, %3;" : "=l"(d) : "l"(a), "l"(b), "l"(c));
    return d;
}
__device__ __forceinline__ ull add2(ull a, ull b) {
    ull d; asm("add.rn.f32x2 %0, %1, %2;" : "=l"(d) : "l"(a), "l"(b));
    return d;
}
__device__ __forceinline__ float2 up2(ull v) {
    float2 r; asm("mov.b64 {%0, %1}, %2;" : "=f"(r.x), "=f"(r.y) : "l"(v)); return r;
}
__device__ __forceinline__ float tanhapx(float v) {
    float r; asm("tanh.approx.f32 %0, %1;" : "=f"(r) : "f"(v)); return r;
}
__device__ __forceinline__ float fsig(float v) {
    return fmaf(0.5f, tanhapx(0.5f * v), 0.5f);
}

__global__ __launch_bounds__(NT, 1) void gru_kernel(
    const float* __restrict__ x, const float* __restrict__ W_ih,
    const float* __restrict__ W_hh, const float* __restrict__ b_ih,
    const float* __restrict__ b_hh, const float* __restrict__ W_out,
    const float* __restrict__ b_out, float* __restrict__ out)
{
    extern __shared__ float sm[];
    float* Wp = sm;                      // [KTOT][32 tiles][WPT]: wr0,wr1,wz0,wz1,wn0,wn1,6xpad
    float* bi = Wp + KTOT * 32 * WPT;    // [RPAD] b_ih (zero-padded)
    float* bh = bi + RPAD;               // [RPAD] b_hh
    float* hx = bh + RPAD;               // [2 groups][2 bufs][KTOT][NBG]

    const int tid  = threadIdx.x;
    const int lane = tid & 31;
    const int wid  = tid >> 5;
    const int gid  = wid >> 2;            // group 0 / 1
    const int gwid = wid & 3;             // warp within group (== its SMSP)
    const int tidg = tid & 127;
    const int tile = tidg >> 2;           // 0..31 (25 live)
    const int c    = tile * 2;
    const int bg4  = (tidg & 3) * 4;      // batch offset within group
    const bool live = (c < HID);
    const int b0   = blockIdx.x * 32 + gid * NBG;

    float* hxg = hx + gid * 2 * HXS;

    // ---- one-time: pack weights, 48B tile stride ----
    for (int i = tid; i < KTOT * 32 * WPT; i += NT) {
        int k  = i / (32 * WPT);
        int r  = i - k * (32 * WPT);
        int tl = r / WPT;
        int q  = r - tl * WPT;
        float v = 0.0f;
        if (q < 6) {
            int g = q >> 1, u = q & 1;
            int cu = tl * 2 + u;
            if (cu < HID) {
                int j = g * HID + cu;
                v = (k < HID) ? W_hh[j * HID + k] : W_ih[j * IN_DIM + (k - HID)];
            }
        }
        Wp[i] = v;
    }
    for (int j = tid; j < RPAD; j += NT) {
        bi[j] = (j < ROWS) ? b_ih[j] : 0.0f;
        bh[j] = (j < ROWS) ? b_hh[j] : 0.0f;
    }
    // zero h rows of both groups' buffer 0
    for (int i = tid; i < HID * NBG; i += NT) { hx[i] = 0.0f; hx[2 * HXS + i] = 0.0f; }

    // ---- x duty: warp 3 of each group, lanes 16..31 (all-dead tiles 28-31) ----
    const bool xduty = (gwid == 3) && (lane >= 16);
    const int  xb    = lane - 16;            // local batch 0..15
    float4 xa, xbv;
    const float* xrow = nullptr;
    if (xduty) {
        xrow = x + (size_t)(b0 + xb) * TLEN * IN_DIM;
        float4 a0 = *(const float4*)&xrow[0];
        float4 a1 = *(const float4*)&xrow[4];
        hxg[(HID + 0) * NBG + xb] = a0.x; hxg[(HID + 1) * NBG + xb] = a0.y;
        hxg[(HID + 2) * NBG + xb] = a0.z; hxg[(HID + 3) * NBG + xb] = a0.w;
        hxg[(HID + 4) * NBG + xb] = a1.x; hxg[(HID + 5) * NBG + xb] = a1.y;
        hxg[(HID + 6) * NBG + xb] = a1.z; hxg[(HID + 7) * NBG + xb] = a1.w;
        xa  = *(const float4*)&xrow[IN_DIM];
        xbv = *(const float4*)&xrow[IN_DIM + 4];
    }
    __syncthreads();   // full: weights + initial state visible to both groups

    ull bsi[3], bbh[3];
    #pragma unroll
    for (int g = 0; g < 3; g++) {
        bsi[g] = *(const ull*)&bi[c + 50 * g];
        bbh[g] = *(const ull*)&bh[c + 50 * g];
    }

    const int barid = gid + 1;

    for (int t = 0; t < TLEN; t++) {
        float* hcur = hxg + (t & 1) * HXS;
        float* hnxt = hxg + ((t + 1) & 1) * HXS;

        // ---- GEMM: x-part first (k=50..57), acc init = b_ih ----
        ull acc[3][4];
        #pragma unroll
        for (int g = 0; g < 3; g++)
            #pragma unroll
            for (int v = 0; v < 4; v++) acc[g][v] = bsi[g];

        #pragma unroll
        for (int k = HID; k < KTOT; k++) {
            const float* wrow = &Wp[(k * 32 + tile) * WPT];
            ulonglong2 wrz = *(const ulonglong2*)wrow;
            ull wn = *(const ull*)(wrow + 4);
            float4 hq = *(const float4*)&hcur[k * NBG + bg4];
            ull hp[4] = {pk2(hq.x), pk2(hq.y), pk2(hq.z), pk2(hq.w)};
            #pragma unroll
            for (int v = 0; v < 4; v++) {
                acc[0][v] = ff2(hp[v], wrz.x, acc[0][v]);
                acc[1][v] = ff2(hp[v], wrz.y, acc[1][v]);
                acc[2][v] = ff2(hp[v], wn,    acc[2][v]);
            }
        }
        ull gis[4];
        #pragma unroll
        for (int v = 0; v < 4; v++) gis[v] = acc[2][v];
        #pragma unroll
        for (int g = 0; g < 3; g++)
            #pragma unroll
            for (int v = 0; v < 4; v++) acc[g][v] = add2(acc[g][v], bbh[g]);

        // ---- h-part (k=0..49) ----
        #pragma unroll
        for (int k = 0; k < HID; k++) {
            const float* wrow = &Wp[(k * 32 + tile) * WPT];
            ulonglong2 wrz = *(const ulonglong2*)wrow;
            ull wn = *(const ull*)(wrow + 4);
            float4 hq = *(const float4*)&hcur[k * NBG + bg4];
            ull hp[4] = {pk2(hq.x), pk2(hq.y), pk2(hq.z), pk2(hq.w)};
            #pragma unroll
            for (int v = 0; v < 4; v++) {
                acc[0][v] = ff2(hp[v], wrz.x, acc[0][v]);
                acc[1][v] = ff2(hp[v], wrz.y, acc[1][v]);
                acc[2][v] = ff2(hp[v], wn,    acc[2][v]);
            }
        }

        // ---- gates in-register; write h(t+1) ----
        if (live) {
            float4 ho0 = *(const float4*)&hcur[c * NBG + bg4];
            float4 ho1 = *(const float4*)&hcur[(c + 1) * NBG + bg4];
            const float* o0 = (const float*)&ho0;
            const float* o1 = (const float*)&ho1;
            float hn0[4], hn1[4];
            #pragma unroll
            for (int v = 0; v < 4; v++) {
                float2 sr = up2(acc[0][v]);
                float2 sz = up2(acc[1][v]);
                float2 sn = up2(acc[2][v]);
                float2 gi = up2(gis[v]);
                float r0 = fsig(sr.x), z0 = fsig(sz.x);
                float n0 = tanhapx(sn.x + (r0 - 1.0f) * (sn.x - gi.x));
                hn0[v] = n0 + z0 * (o0[v] - n0);
                float r1 = fsig(sr.y), z1 = fsig(sz.y);
                float n1 = tanhapx(sn.y + (r1 - 1.0f) * (sn.y - gi.y));
                hn1[v] = n1 + z1 * (o1[v] - n1);
            }
            *(float4*)&hnxt[c * NBG + bg4]       = make_float4(hn0[0], hn0[1], hn0[2], hn0[3]);
            *(float4*)&hnxt[(c + 1) * NBG + bg4] = make_float4(hn1[0], hn1[1], hn1[2], hn1[3]);
        }

        // ---- x publish / prefetch (dead lanes of warp 3) ----
        if (xduty && t + 1 < TLEN) {
            hnxt[(HID + 0) * NBG + xb] = xa.x;  hnxt[(HID + 1) * NBG + xb] = xa.y;
            hnxt[(HID + 2) * NBG + xb] = xa.z;  hnxt[(HID + 3) * NBG + xb] = xa.w;
            hnxt[(HID + 4) * NBG + xb] = xbv.x; hnxt[(HID + 5) * NBG + xb] = xbv.y;
            hnxt[(HID + 6) * NBG + xb] = xbv.z; hnxt[(HID + 7) * NBG + xb] = xbv.w;
            if (t + 2 < TLEN) {
                xa  = *(const float4*)&xrow[(size_t)(t + 2) * IN_DIM];
                xbv = *(const float4*)&xrow[(size_t)(t + 2) * IN_DIM + 4];
            }
        }

        // group-local barrier: only this group's 128 threads
        asm volatile("bar.sync %0, %1;" :: "r"(barid), "r"(128) : "memory");
    }
    __syncthreads();   // join both groups before the head

    // linear head on final hidden state (buffer 0 of each group)
    if (tid < 32) {
        int g  = tid >> 4;
        int bl = tid & 15;
        const float* hfin = hx + g * 2 * HXS;
        float acc = b_out[0];
        #pragma unroll
        for (int cc = 0; cc < HID; cc++) acc += hfin[cc * NBG + bl] * W_out[cc];
        out[blockIdx.x * 32 + tid] = acc;
    }
}

extern "C" void kernel_launch(void* const* d_in, const int* in_sizes, int n_in,
                              void* d_out, int out_size) {
    const float* x     = (const float*)d_in[0];
    const float* W_ih  = (const float*)d_in[1];
    const float* W_hh  = (const float*)d_in[2];
    const float* b_ih  = (const float*)d_in[3];
    const float* b_hh  = (const float*)d_in[4];
    const float* W_out = (const float*)d_in[5];
    const float* b_out = (const float*)d_in[6];
    float* out = (float*)d_out;

    size_t smem = (size_t)(KTOT * 32 * WPT + 2 * RPAD + 4 * HXS) * sizeof(float);
    cudaFuncSetAttribute(gru_kernel,
                         cudaFuncAttributeMaxDynamicSharedMemorySize, (int)smem);
    gru_kernel<<<GRIDN, NT, smem>>>(x, W_ih, W_hh, b_ih, b_hh, W_out, b_out, out);
}